// round 4
// baseline (speedup 1.0000x reference)
#include <cuda_runtime.h>
#include <cstdint>

#define N_NODES 50000
#define N_EDGES 1600000
#define IN_CH 256
#define AD 64
#define ED 32
#define SCAN_B 512
#define NBLK ((N_NODES + SCAN_B - 1) / SCAN_B)   // 98

typedef unsigned long long ull;

// ---------------- scratch (device globals; no allocations allowed) ----------------
__device__ int   g_cnt[N_NODES];
__device__ int   g_off[N_NODES + 1];
__device__ int   g_cur[N_NODES];
__device__ int   g_eid[N_EDGES];
__device__ int   g_bsum[NBLK];
__device__ int   g_bsumoff[NBLK];
__device__ float g_ntf[N_NODES * AD];
__device__ float g_h1[N_NODES * AD];
__device__ float g_fus[N_NODES * AD];
__device__ int   g_is64;

// ---------------- f32x2 packed-FMA helpers ----------------
__device__ __forceinline__ void ffma2(ull& d, ull a, ull b) {
    asm("fma.rn.f32x2 %0, %1, %2, %0;" : "+l"(d) : "l"(a), "l"(b));
}
__device__ __forceinline__ float2 unpack2(ull p) {
    float2 r; asm("mov.b64 {%0, %1}, %2;" : "=f"(r.x), "=f"(r.y) : "l"(p)); return r;
}
__device__ __forceinline__ ull pack2(float x, float y) {
    ull p; asm("mov.b64 %0, {%1, %2};" : "=l"(p) : "f"(x), "f"(y)); return p;
}

// ---------------- edge_index dtype detection ----------------
__global__ void detect_kernel(const unsigned int* __restrict__ idx_words) {
    if (threadIdx.x == 0 && blockIdx.x == 0) {
        int ok = 1;
        #pragma unroll 1
        for (int i = 0; i < 64; i++)
            if (idx_words[2 * i + 1] != 0u) { ok = 0; break; }
        g_is64 = ok;
    }
}

__global__ void zero_cnt_kernel() {
    int i = blockIdx.x * blockDim.x + threadIdx.x;
    if (i < N_NODES) g_cnt[i] = 0;
}

__device__ __forceinline__ int load_src(const void* ei, int e) {
    return g_is64 ? (int)((const long long*)ei)[e] : ((const int*)ei)[e];
}

__global__ void hist_kernel(const void* __restrict__ ei) {
    int e = blockIdx.x * blockDim.x + threadIdx.x;
    if (e < N_EDGES) atomicAdd(&g_cnt[load_src(ei, e)], 1);
}

// ---------------- 3-phase exclusive scan of g_cnt -> g_off ----------------
__global__ void scan1_kernel() {
    __shared__ int s[SCAN_B];
    int tid = threadIdx.x;
    int i = blockIdx.x * SCAN_B + tid;
    int v = (i < N_NODES) ? g_cnt[i] : 0;
    s[tid] = v; __syncthreads();
    for (int d = 1; d < SCAN_B; d <<= 1) {
        int t = (tid >= d) ? s[tid - d] : 0;
        __syncthreads();
        s[tid] += t;
        __syncthreads();
    }
    if (i < N_NODES) g_off[i] = s[tid] - v;     // block-local exclusive
    if (tid == SCAN_B - 1) g_bsum[blockIdx.x] = s[tid];
}

__global__ void scan2_kernel() {
    __shared__ int s[128];
    int tid = threadIdx.x;
    int v = (tid < NBLK) ? g_bsum[tid] : 0;
    s[tid] = v; __syncthreads();
    for (int d = 1; d < 128; d <<= 1) {
        int t = (tid >= d) ? s[tid - d] : 0;
        __syncthreads();
        s[tid] += t;
        __syncthreads();
    }
    if (tid < NBLK) g_bsumoff[tid] = s[tid] - v;
}

__global__ void scan3_kernel() {
    int tid = threadIdx.x;
    int i = blockIdx.x * SCAN_B + tid;
    if (i < N_NODES) {
        int o = g_off[i] + g_bsumoff[blockIdx.x];
        g_off[i] = o;
        g_cur[i] = o;
    }
    if (blockIdx.x == 0 && tid == 0) g_off[N_NODES] = N_EDGES;
}

__global__ void fill_kernel(const void* __restrict__ ei) {
    int e = blockIdx.x * blockDim.x + threadIdx.x;
    if (e < N_EDGES) {
        int src = load_src(ei, e);
        int pos = atomicAdd(&g_cur[src], 1);
        g_eid[pos] = e;
    }
}

// ---------------- aggregate: per-node gather, W_time in registers, no atomics ----------------
__global__ __launch_bounds__(256) void agg_kernel(
    const float* __restrict__ edge_attr,
    const float* __restrict__ W_time,
    const float* __restrict__ b_time)
{
    int lane = threadIdx.x & 31, warp = threadIdx.x >> 5;
    // lane owns output rows j=lane and j=lane+32; weights as k-pair-packed ull
    ull wA[16], wB[16];
    const ull* rA = (const ull*)(W_time + lane * ED);
    const ull* rB = (const ull*)(W_time + (lane + 32) * ED);
    #pragma unroll
    for (int i = 0; i < 16; i++) { wA[i] = rA[i]; wB[i] = rB[i]; }
    float bA = b_time[lane], bB = b_time[lane + 32];

    int gw = blockIdx.x * 8 + warp;
    int nw = gridDim.x * 8;
    for (int n = gw; n < N_NODES; n += nw) {
        int o0 = g_off[n], o1 = g_off[n + 1];
        float sA = 0.f, sB = 0.f;
        for (int base = o0; base < o1; base += 32) {
            int cnt = min(32, o1 - base);
            int myid = (base + lane < o1) ? g_eid[base + lane] : 0;
            for (int ii = 0; ii < cnt; ii++) {
                int eid = __shfl_sync(0xffffffffu, myid, ii);
                const ulonglong2* ea = (const ulonglong2*)(edge_attr + (size_t)eid * ED);
                ulonglong2 vv[8];
                #pragma unroll
                for (int i = 0; i < 8; i++) vv[i] = ea[i];
                ull a0 = 0, a1 = 0, b0 = 0, b1 = 0;
                #pragma unroll
                for (int i = 0; i < 8; i++) {
                    ffma2(a0, vv[i].x, wA[2 * i]);
                    ffma2(a1, vv[i].y, wA[2 * i + 1]);
                    ffma2(b0, vv[i].x, wB[2 * i]);
                    ffma2(b1, vv[i].y, wB[2 * i + 1]);
                }
                float2 pa0 = unpack2(a0), pa1 = unpack2(a1);
                float2 pb0 = unpack2(b0), pb1 = unpack2(b1);
                sA += fmaxf(pa0.x + pa0.y + pa1.x + pa1.y + bA, 0.f);
                sB += fmaxf(pb0.x + pb0.y + pb1.x + pb1.y + bB, 0.f);
            }
        }
        float c = fmaxf((float)(o1 - o0), 1.0f);
        g_ntf[(size_t)n * AD + lane]      = sA / c;
        g_ntf[(size_t)n * AD + lane + 32] = sB / c;
    }
}

// ---------------- down-proj GEMM: h1 = relu(x @ Wd^T + bd), 8 nodes/warp ----------------
// smem: sW [64][129] ull (rows j, k-pair packed, pad 1 vs conflicts), xbuf 8w*8n*128 ull
#define DN_SMEM (size_t)(64 * 129 * 8 + 8 * 8 * 128 * 8 + 64 * 4)
__global__ __launch_bounds__(256) void down_kernel(
    const float* __restrict__ x,
    const float* __restrict__ W_down,
    const float* __restrict__ b_down)
{
    extern __shared__ __align__(16) char dsm[];
    ull*   sW = (ull*)dsm;                 // 64*129
    ull*   xb = sW + 64 * 129;             // 8 warps * 1024
    float* sB = (float*)(xb + 8 * 1024);   // 64
    int tid = threadIdx.x;
    const ull* wsrc = (const ull*)W_down;  // [64][128] k-pairs
    for (int i = tid; i < 64 * 128; i += 256) {
        int j = i >> 7, kp = i & 127;
        sW[j * 129 + kp] = wsrc[i];
    }
    if (tid < 64) sB[tid] = b_down[tid];
    __syncthreads();

    int lane = tid & 31, warp = tid >> 5;
    ull* xw = xb + warp * 1024;
    const ull* wAp = sW + lane * 129;
    const ull* wBp = sW + (lane + 32) * 129;
    int stride = gridDim.x * 64;
    for (int n0 = (blockIdx.x * 8 + warp) * 8; n0 < N_NODES; n0 += stride) {
        int nval = min(8, N_NODES - n0);
        for (int r = 0; r < nval; r++) {
            const ulonglong2* src = (const ulonglong2*)(x + (size_t)(n0 + r) * IN_CH);
            ulonglong2* dst = (ulonglong2*)(xw + r * 128);
            dst[lane] = src[lane];
            dst[lane + 32] = src[lane + 32];
        }
        __syncwarp();
        ull aA[8], aB[8];
        #pragma unroll
        for (int r = 0; r < 8; r++) { aA[r] = 0; aB[r] = 0; }
        #pragma unroll 4
        for (int kp = 0; kp < 128; kp++) {
            ull wa = wAp[kp], wb = wBp[kp];
            #pragma unroll
            for (int r = 0; r < 8; r++) {
                ull xv = xw[r * 128 + kp];
                ffma2(aA[r], xv, wa);
                ffma2(aB[r], xv, wb);
            }
        }
        #pragma unroll
        for (int r = 0; r < 8; r++) {
            if (r < nval) {
                float2 p = unpack2(aA[r]);
                float2 q = unpack2(aB[r]);
                g_h1[(size_t)(n0 + r) * AD + lane]      = fmaxf(p.x + p.y + sB[lane], 0.f);
                g_h1[(size_t)(n0 + r) * AD + lane + 32] = fmaxf(q.x + q.y + sB[lane + 32], 0.f);
            }
        }
        __syncwarp();
    }
}

// ---------------- fusion GEMM: fus = relu([h1|ntf] @ Wf^T + bf), 8 nodes/warp ----------------
#define FU_SMEM (size_t)(64 * 65 * 8 + 8 * 8 * 64 * 8 + 64 * 4)
__global__ __launch_bounds__(256) void fusion_kernel(
    const float* __restrict__ W_fusion,
    const float* __restrict__ b_fusion)
{
    extern __shared__ __align__(16) char fsm[];
    ull*   sW = (ull*)fsm;                // 64*65
    ull*   cb = sW + 64 * 65;             // 8 warps * 512
    float* sB = (float*)(cb + 8 * 512);   // 64
    int tid = threadIdx.x;
    const ull* wsrc = (const ull*)W_fusion;  // [64][64] k-pairs
    for (int i = tid; i < 64 * 64; i += 256) {
        int j = i >> 6, kp = i & 63;
        sW[j * 65 + kp] = wsrc[i];
    }
    if (tid < 64) sB[tid] = b_fusion[tid];
    __syncthreads();

    int lane = tid & 31, warp = tid >> 5;
    ull* cw = cb + warp * 512;
    const ull* wAp = sW + lane * 65;
    const ull* wBp = sW + (lane + 32) * 65;
    int stride = gridDim.x * 64;
    for (int n0 = (blockIdx.x * 8 + warp) * 8; n0 < N_NODES; n0 += stride) {
        int nval = min(8, N_NODES - n0);
        for (int r = 0; r < nval; r++) {
            const ull* h1r = (const ull*)(g_h1 + (size_t)(n0 + r) * AD);
            const ull* ntr = (const ull*)(g_ntf + (size_t)(n0 + r) * AD);
            ull* dst = cw + r * 64;
            dst[lane] = h1r[lane];
            dst[32 + lane] = ntr[lane];
        }
        __syncwarp();
        ull aA[8], aB[8];
        #pragma unroll
        for (int r = 0; r < 8; r++) { aA[r] = 0; aB[r] = 0; }
        #pragma unroll 4
        for (int kp = 0; kp < 64; kp++) {
            ull wa = wAp[kp], wb = wBp[kp];
            #pragma unroll
            for (int r = 0; r < 8; r++) {
                ull xv = cw[r * 64 + kp];
                ffma2(aA[r], xv, wa);
                ffma2(aB[r], xv, wb);
            }
        }
        #pragma unroll
        for (int r = 0; r < 8; r++) {
            if (r < nval) {
                float2 p = unpack2(aA[r]);
                float2 q = unpack2(aB[r]);
                g_fus[(size_t)(n0 + r) * AD + lane]      = fmaxf(p.x + p.y + sB[lane], 0.f);
                g_fus[(size_t)(n0 + r) * AD + lane + 32] = fmaxf(q.x + q.y + sB[lane + 32], 0.f);
            }
        }
        __syncwarp();
    }
}

// ---------------- up-proj GEMM + residual: out = fus @ Wu^T + bu + x, 4 nodes/warp ----------
// weights packed (o, o+128) as float2 in layout [k][o128] -> conflict-free lane loads
#define UP_SMEM (size_t)(64 * 128 * 8 + 8 * 4 * 32 * 8 + 256 * 4)
__global__ __launch_bounds__(256) void up_kernel(
    const float* __restrict__ x,
    const float* __restrict__ W_up,
    const float* __restrict__ b_up,
    float* __restrict__ out)
{
    extern __shared__ __align__(16) char usm[];
    ull*   sW = (ull*)usm;                 // [64][128]
    ull*   fb = sW + 64 * 128;             // 8 warps * 4 nodes * 32
    float* sB = (float*)(fb + 8 * 4 * 32); // 256
    int tid = threadIdx.x;
    for (int i = tid; i < 64 * 128; i += 256) {
        int k = i >> 7, o = i & 127;
        sW[i] = pack2(W_up[o * AD + k], W_up[(o + 128) * AD + k]);
    }
    if (tid < 256) sB[tid] = b_up[tid];
    __syncthreads();

    int lane = tid & 31, warp = tid >> 5;
    ull* fw = fb + warp * 128;
    const float* fwf = (const float*)fw;
    int stride = gridDim.x * 32;
    for (int n0 = (blockIdx.x * 8 + warp) * 4; n0 < N_NODES; n0 += stride) {
        int nval = min(4, N_NODES - n0);
        for (int r = 0; r < nval; r++) {
            const ull* fr = (const ull*)(g_fus + (size_t)(n0 + r) * AD);
            fw[r * 32 + lane] = fr[lane];
        }
        __syncwarp();
        ull acc[4][4];
        #pragma unroll
        for (int r = 0; r < 4; r++)
            #pragma unroll
            for (int t = 0; t < 4; t++) acc[r][t] = 0;
        #pragma unroll 2
        for (int k = 0; k < AD; k++) {
            ull w0 = sW[k * 128 + lane];
            ull w1 = sW[k * 128 + lane + 32];
            ull w2 = sW[k * 128 + lane + 64];
            ull w3 = sW[k * 128 + lane + 96];
            #pragma unroll
            for (int r = 0; r < 4; r++) {
                float fv = fwf[r * 64 + k];
                ull fp = pack2(fv, fv);
                ffma2(acc[r][0], fp, w0);
                ffma2(acc[r][1], fp, w1);
                ffma2(acc[r][2], fp, w2);
                ffma2(acc[r][3], fp, w3);
            }
        }
        #pragma unroll
        for (int r = 0; r < 4; r++) {
            if (r < nval) {
                size_t base = (size_t)(n0 + r) * IN_CH;
                #pragma unroll
                for (int t = 0; t < 4; t++) {
                    float2 p = unpack2(acc[r][t]);
                    int o = lane + 32 * t;
                    out[base + o]       = p.x + sB[o]       + x[base + o];
                    out[base + o + 128] = p.y + sB[o + 128] + x[base + o + 128];
                }
            }
        }
        __syncwarp();
    }
}

// ---------------- launch ----------------
extern "C" void kernel_launch(void* const* d_in, const int* in_sizes, int n_in,
                              void* d_out, int out_size)
{
    const float* x        = (const float*)d_in[0];
    const void*  eidx     = d_in[1];
    const float* eattr    = (const float*)d_in[2];
    const float* W_down   = (const float*)d_in[3];
    const float* b_down   = (const float*)d_in[4];
    const float* W_time   = (const float*)d_in[5];
    const float* b_time   = (const float*)d_in[6];
    const float* W_fusion = (const float*)d_in[7];
    const float* b_fusion = (const float*)d_in[8];
    const float* W_up     = (const float*)d_in[9];
    const float* b_up     = (const float*)d_in[10];
    float* out = (float*)d_out;

    cudaFuncSetAttribute(down_kernel,   cudaFuncAttributeMaxDynamicSharedMemorySize, (int)DN_SMEM);
    cudaFuncSetAttribute(fusion_kernel, cudaFuncAttributeMaxDynamicSharedMemorySize, (int)FU_SMEM);
    cudaFuncSetAttribute(up_kernel,     cudaFuncAttributeMaxDynamicSharedMemorySize, (int)UP_SMEM);

    detect_kernel<<<1, 32>>>((const unsigned int*)eidx);
    zero_cnt_kernel<<<(N_NODES + 255) / 256, 256>>>();
    hist_kernel<<<(N_EDGES + 255) / 256, 256>>>(eidx);
    scan1_kernel<<<NBLK, SCAN_B>>>();
    scan2_kernel<<<1, 128>>>();
    scan3_kernel<<<NBLK, SCAN_B>>>();
    fill_kernel<<<(N_EDGES + 255) / 256, 256>>>(eidx);
    agg_kernel<<<148, 256>>>(eattr, W_time, b_time);
    down_kernel<<<148, 256, DN_SMEM>>>(x, W_down, b_down);
    fusion_kernel<<<296, 256, FU_SMEM>>>(W_fusion, b_fusion);
    up_kernel<<<296, 256, UP_SMEM>>>(x, W_up, b_up, out);
}

// round 7
// speedup vs baseline: 1.6427x; 1.6427x over previous
#include <cuda_runtime.h>
#include <cstdint>

#define N_NODES 50000
#define N_EDGES 1600000
#define IN_CH 256
#define AD 64
#define ED 32
#define SCAN_B 512
#define NBLK ((N_NODES + SCAN_B - 1) / SCAN_B)   // 98

typedef unsigned long long ull;

// ---------------- scratch (device globals; no allocations allowed) ----------------
__device__ int   g_cnt[N_NODES];
__device__ int   g_off[N_NODES + 1];
__device__ int   g_cur[N_NODES];
__device__ int   g_eid[N_EDGES];
__device__ int   g_srcs[N_EDGES];       // src per slot, sorted by node (CSR order)
__device__ int   g_bsum[NBLK];
__device__ int   g_bsumoff[NBLK];
__device__ float g_sums[N_NODES * AD];  // relu(time_feat) segment sums
__device__ float g_h1[N_NODES * AD];
__device__ int   g_is64;

// ---------------- f32x2 packed-FMA helpers ----------------
__device__ __forceinline__ void ffma2(ull& d, ull a, ull b) {
    asm("fma.rn.f32x2 %0, %1, %2, %0;" : "+l"(d) : "l"(a), "l"(b));
}
__device__ __forceinline__ float2 unpack2(ull p) {
    float2 r; asm("mov.b64 {%0, %1}, %2;" : "=f"(r.x), "=f"(r.y) : "l"(p)); return r;
}
__device__ __forceinline__ ull pack2(float x, float y) {
    ull p; asm("mov.b64 %0, {%1, %2};" : "=l"(p) : "f"(x), "f"(y)); return p;
}

// ---------------- edge_index dtype detection ----------------
__global__ void detect_kernel(const unsigned int* __restrict__ idx_words) {
    if (threadIdx.x == 0 && blockIdx.x == 0) {
        int ok = 1;
        #pragma unroll 1
        for (int i = 0; i < 64; i++)
            if (idx_words[2 * i + 1] != 0u) { ok = 0; break; }
        g_is64 = ok;
    }
}

// zero g_cnt and g_sums
__global__ void zero_kernel() {
    int i = blockIdx.x * blockDim.x + threadIdx.x;
    if (i < N_NODES * AD / 4) reinterpret_cast<float4*>(g_sums)[i] = make_float4(0.f, 0.f, 0.f, 0.f);
    if (i < N_NODES) g_cnt[i] = 0;
}

__device__ __forceinline__ int load_src(const void* ei, int e) {
    return g_is64 ? (int)((const long long*)ei)[e] : ((const int*)ei)[e];
}

__global__ void hist_kernel(const void* __restrict__ ei) {
    int e = blockIdx.x * blockDim.x + threadIdx.x;
    if (e < N_EDGES) atomicAdd(&g_cnt[load_src(ei, e)], 1);
}

// ---------------- 3-phase exclusive scan of g_cnt -> g_off ----------------
__global__ void scan1_kernel() {
    __shared__ int s[SCAN_B];
    int tid = threadIdx.x;
    int i = blockIdx.x * SCAN_B + tid;
    int v = (i < N_NODES) ? g_cnt[i] : 0;
    s[tid] = v; __syncthreads();
    for (int d = 1; d < SCAN_B; d <<= 1) {
        int t = (tid >= d) ? s[tid - d] : 0;
        __syncthreads();
        s[tid] += t;
        __syncthreads();
    }
    if (i < N_NODES) g_off[i] = s[tid] - v;
    if (tid == SCAN_B - 1) g_bsum[blockIdx.x] = s[tid];
}

__global__ void scan2_kernel() {
    __shared__ int s[128];
    int tid = threadIdx.x;
    int v = (tid < NBLK) ? g_bsum[tid] : 0;
    s[tid] = v; __syncthreads();
    for (int d = 1; d < 128; d <<= 1) {
        int t = (tid >= d) ? s[tid - d] : 0;
        __syncthreads();
        s[tid] += t;
        __syncthreads();
    }
    if (tid < NBLK) g_bsumoff[tid] = s[tid] - v;
}

__global__ void scan3_kernel() {
    int tid = threadIdx.x;
    int i = blockIdx.x * SCAN_B + tid;
    if (i < N_NODES) {
        int o = g_off[i] + g_bsumoff[blockIdx.x];
        g_off[i] = o;
        g_cur[i] = o;
    }
    if (blockIdx.x == 0 && tid == 0) g_off[N_NODES] = N_EDGES;
}

__global__ void fill_kernel(const void* __restrict__ ei) {
    int e = blockIdx.x * blockDim.x + threadIdx.x;
    if (e < N_EDGES) {
        int src = load_src(ei, e);
        int pos = atomicAdd(&g_cur[src], 1);
        g_eid[pos] = e;
        g_srcs[pos] = src;
    }
}

// ---------------- edge kernel: 32 consecutive CSR edges per warp --------------------
// Lane gathers its own edge row (8 independent LDG.128 = one 128B line) -> smem
// transpose -> all lanes compute each edge's outputs (W_time in regs, f32x2 FMA).
// Segment-boundary flush via ballot mask: ~2 scalar reds/lane/node instead of 16 v4/edge.
#define EW 8   // warps per block; 1.6M/32 = 50000 chunks, grid = 6250
__global__ __launch_bounds__(256) void edge_kernel(
    const float* __restrict__ edge_attr,
    const float* __restrict__ W_time,
    const float* __restrict__ b_time)
{
    __shared__ __align__(16) ull sbuf[EW][32][17];   // [warp][edge][k-pair], pad 17
    int lane = threadIdx.x & 31, warp = threadIdx.x >> 5;
    int e0 = (blockIdx.x * EW + warp) * 32;

    // W_time rows (j = lane, lane+32) as k-pair-packed registers
    ull wA[16], wB[16];
    const ull* rA = (const ull*)(W_time + lane * ED);
    const ull* rB = (const ull*)(W_time + (lane + 32) * ED);
    #pragma unroll
    for (int i = 0; i < 16; i++) { wA[i] = rA[i]; wB[i] = rB[i]; }
    float bA = b_time[lane], bB = b_time[lane + 32];

    int eid = g_eid[e0 + lane];
    int src = g_srcs[e0 + lane];

    // gather own edge row (one 128B line), transpose into smem
    const float4* ea = (const float4*)(edge_attr + (size_t)eid * ED);
    ull* row = sbuf[warp][lane];
    #pragma unroll
    for (int i = 0; i < 8; i++) {
        float4 v = ea[i];
        row[2 * i]     = pack2(v.x, v.y);
        row[2 * i + 1] = pack2(v.z, v.w);
    }
    int prev = __shfl_up_sync(0xffffffffu, src, 1);
    unsigned bmask = __ballot_sync(0xffffffffu, lane > 0 && src != prev);
    __syncwarp();

    float sA = 0.f, sB = 0.f;
    int cur = __shfl_sync(0xffffffffu, src, 0);
    #pragma unroll 4
    for (int ii = 0; ii < 32; ii++) {
        if ((bmask >> ii) & 1u) {           // uniform branch
            float* dst = g_sums + (size_t)cur * AD;
            asm volatile("red.global.add.f32 [%0], %1;" :: "l"(dst + lane), "f"(sA) : "memory");
            asm volatile("red.global.add.f32 [%0], %1;" :: "l"(dst + lane + 32), "f"(sB) : "memory");
            sA = 0.f; sB = 0.f;
            cur = __shfl_sync(0xffffffffu, src, ii);
        }
        const ull* er = sbuf[warp][ii];     // broadcast reads
        ull a0 = 0, a1 = 0, b0 = 0, b1 = 0;
        #pragma unroll
        for (int i = 0; i < 8; i++) {
            ull e_lo = er[2 * i], e_hi = er[2 * i + 1];
            ffma2(a0, e_lo, wA[2 * i]);
            ffma2(a1, e_hi, wA[2 * i + 1]);
            ffma2(b0, e_lo, wB[2 * i]);
            ffma2(b1, e_hi, wB[2 * i + 1]);
        }
        float2 p0 = unpack2(a0), p1 = unpack2(a1);
        float2 q0 = unpack2(b0), q1 = unpack2(b1);
        sA += fmaxf(p0.x + p0.y + p1.x + p1.y + bA, 0.f);
        sB += fmaxf(q0.x + q0.y + q1.x + q1.y + bB, 0.f);
    }
    float* dst = g_sums + (size_t)cur * AD;
    asm volatile("red.global.add.f32 [%0], %1;" :: "l"(dst + lane), "f"(sA) : "memory");
    asm volatile("red.global.add.f32 [%0], %1;" :: "l"(dst + lane + 32), "f"(sB) : "memory");
}

// ---------------- down-proj GEMM: h1 = relu(x @ Wd^T + bd), 8 nodes/warp ----------------
// weights [kp][j] in smem (row stride 65 ull) -> lane-consecutive, conflict-free
#define DN_WARPS 16
#define DN_SMEM (size_t)(128 * 65 * 8 + DN_WARPS * 1024 * 8 + 64 * 4)
__global__ __launch_bounds__(512) void down_kernel(
    const float* __restrict__ x,
    const float* __restrict__ W_down,
    const float* __restrict__ b_down)
{
    extern __shared__ __align__(16) char dsm[];
    ull*   sW = (ull*)dsm;                       // [128 kp][65]
    ull*   xb = sW + 128 * 65;                   // 16 warps * 1024
    float* sB = (float*)(xb + DN_WARPS * 1024);  // 64
    int tid = threadIdx.x;
    const ull* wsrc = (const ull*)W_down;        // [64 j][128 kp]
    for (int i = tid; i < 64 * 128; i += 512) {
        int j = i >> 7, kp = i & 127;
        sW[kp * 65 + j] = wsrc[i];
    }
    if (tid < 64) sB[tid] = b_down[tid];
    __syncthreads();

    int lane = tid & 31, warp = tid >> 5;
    ull* xw = xb + warp * 1024;
    int stride = gridDim.x * DN_WARPS * 8;
    for (int n0 = (blockIdx.x * DN_WARPS + warp) * 8; n0 < N_NODES; n0 += stride) {
        int nval = min(8, N_NODES - n0);
        for (int r = 0; r < nval; r++) {
            const ulonglong2* src = (const ulonglong2*)(x + (size_t)(n0 + r) * IN_CH);
            ulonglong2* dst = (ulonglong2*)(xw + r * 128);
            dst[lane] = src[lane];
            dst[lane + 32] = src[lane + 32];
        }
        __syncwarp();
        ull aA[8], aB[8];
        #pragma unroll
        for (int r = 0; r < 8; r++) { aA[r] = 0; aB[r] = 0; }
        #pragma unroll 4
        for (int kp = 0; kp < 128; kp++) {
            ull wa = sW[kp * 65 + lane];
            ull wb = sW[kp * 65 + lane + 32];
            #pragma unroll
            for (int r = 0; r < 8; r++) {
                ull xv = xw[r * 128 + kp];
                ffma2(aA[r], xv, wa);
                ffma2(aB[r], xv, wb);
            }
        }
        #pragma unroll
        for (int r = 0; r < 8; r++) {
            if (r < nval) {
                float2 p = unpack2(aA[r]);
                float2 q = unpack2(aB[r]);
                g_h1[(size_t)(n0 + r) * AD + lane]      = fmaxf(p.x + p.y + sB[lane], 0.f);
                g_h1[(size_t)(n0 + r) * AD + lane + 32] = fmaxf(q.x + q.y + sB[lane + 32], 0.f);
            }
        }
        __syncwarp();
    }
}

// ---------------- fused fusion + up-proj + residual, 4 nodes/warp ----------------
#define FU_WARPS 16
// ull counts: sWf 64*65=4160, sWu 64*128=8192, comb 16*256, fusf floats 16*256
#define FU_SMEM (size_t)((4160 + 8192 + FU_WARPS * 256) * 8 + FU_WARPS * 256 * 4 + 64 * 4 + 256 * 4)
__global__ __launch_bounds__(512) void fuseup_kernel(
    const float* __restrict__ x,
    const float* __restrict__ W_fusion, const float* __restrict__ b_fusion,
    const float* __restrict__ W_up,     const float* __restrict__ b_up,
    float* __restrict__ out)
{
    extern __shared__ __align__(16) char fsm[];
    ull*   sWf = (ull*)fsm;                        // [64 kp][65]
    ull*   sWu = sWf + 4160;                       // [64 k][128 o-pair]
    ull*   cb  = sWu + 8192;                       // 16 warps * 256 (comb pairs)
    float* fb  = (float*)(cb + FU_WARPS * 256);    // 16 warps * 256 (fus scalars)
    float* sBf = fb + FU_WARPS * 256;              // 64
    float* sBu = sBf + 64;                         // 256
    int tid = threadIdx.x;
    const ull* wfsrc = (const ull*)W_fusion;       // [64 j][64 kp]
    for (int i = tid; i < 64 * 64; i += 512) {
        int j = i >> 6, kp = i & 63;
        sWf[kp * 65 + j] = wfsrc[i];
    }
    for (int i = tid; i < 64 * 128; i += 512) {
        int k = i >> 7, o = i & 127;
        sWu[i] = pack2(W_up[o * AD + k], W_up[(o + 128) * AD + k]);
    }
    if (tid < 64)  sBf[tid] = b_fusion[tid];
    if (tid < 256) sBu[tid] = b_up[tid];
    __syncthreads();

    int lane = tid & 31, warp = tid >> 5;
    ull*   cw  = cb + warp * 256;    // 4 nodes * 64 pairs
    float* fw  = fb + warp * 256;    // 4 nodes * 64 scalars
    int stride = gridDim.x * FU_WARPS * 4;
    for (int n0 = (blockIdx.x * FU_WARPS + warp) * 4; n0 < N_NODES; n0 += stride) {
        int nval = min(4, N_NODES - n0);
        // build comb = [h1 | sums/cnt]
        for (int r = 0; r < nval; r++) {
            const ull* h1r = (const ull*)(g_h1 + (size_t)(n0 + r) * AD);
            const ull* sur = (const ull*)(g_sums + (size_t)(n0 + r) * AD);
            float inv = 1.0f / fmaxf((float)g_cnt[n0 + r], 1.0f);
            cw[r * 64 + lane] = h1r[lane];
            float2 s = unpack2(sur[lane]);
            cw[r * 64 + 32 + lane] = pack2(s.x * inv, s.y * inv);
        }
        __syncwarp();
        // fusion GEMM
        ull aA[4], aB[4];
        #pragma unroll
        for (int r = 0; r < 4; r++) { aA[r] = 0; aB[r] = 0; }
        #pragma unroll 4
        for (int kp = 0; kp < 64; kp++) {
            ull wa = sWf[kp * 65 + lane];
            ull wb = sWf[kp * 65 + lane + 32];
            #pragma unroll
            for (int r = 0; r < 4; r++) {
                ull cv = cw[r * 64 + kp];
                ffma2(aA[r], cv, wa);
                ffma2(aB[r], cv, wb);
            }
        }
        #pragma unroll
        for (int r = 0; r < 4; r++) {
            float2 p = unpack2(aA[r]);
            float2 q = unpack2(aB[r]);
            fw[r * 64 + lane]      = fmaxf(p.x + p.y + sBf[lane], 0.f);
            fw[r * 64 + lane + 32] = fmaxf(q.x + q.y + sBf[lane + 32], 0.f);
        }
        __syncwarp();
        // up GEMM + bias + residual
        ull acc[4][4];
        #pragma unroll
        for (int r = 0; r < 4; r++)
            #pragma unroll
            for (int t = 0; t < 4; t++) acc[r][t] = 0;
        #pragma unroll 2
        for (int k = 0; k < AD; k++) {
            ull w0 = sWu[k * 128 + lane];
            ull w1 = sWu[k * 128 + lane + 32];
            ull w2 = sWu[k * 128 + lane + 64];
            ull w3 = sWu[k * 128 + lane + 96];
            #pragma unroll
            for (int r = 0; r < 4; r++) {
                float fv = fw[r * 64 + k];
                ull fp = pack2(fv, fv);
                ffma2(acc[r][0], fp, w0);
                ffma2(acc[r][1], fp, w1);
                ffma2(acc[r][2], fp, w2);
                ffma2(acc[r][3], fp, w3);
            }
        }
        #pragma unroll
        for (int r = 0; r < 4; r++) {
            if (r < nval) {
                size_t base = (size_t)(n0 + r) * IN_CH;
                #pragma unroll
                for (int t = 0; t < 4; t++) {
                    float2 p = unpack2(acc[r][t]);
                    int o = lane + 32 * t;
                    out[base + o]       = p.x + sBu[o]       + x[base + o];
                    out[base + o + 128] = p.y + sBu[o + 128] + x[base + o + 128];
                }
            }
        }
        __syncwarp();
    }
}

// ---------------- launch ----------------
extern "C" void kernel_launch(void* const* d_in, const int* in_sizes, int n_in,
                              void* d_out, int out_size)
{
    const float* x        = (const float*)d_in[0];
    const void*  eidx     = d_in[1];
    const float* eattr    = (const float*)d_in[2];
    const float* W_down   = (const float*)d_in[3];
    const float* b_down   = (const float*)d_in[4];
    const float* W_time   = (const float*)d_in[5];
    const float* b_time   = (const float*)d_in[6];
    const float* W_fusion = (const float*)d_in[7];
    const float* b_fusion = (const float*)d_in[8];
    const float* W_up     = (const float*)d_in[9];
    const float* b_up     = (const float*)d_in[10];
    float* out = (float*)d_out;

    cudaFuncSetAttribute(down_kernel,   cudaFuncAttributeMaxDynamicSharedMemorySize, (int)DN_SMEM);
    cudaFuncSetAttribute(fuseup_kernel, cudaFuncAttributeMaxDynamicSharedMemorySize, (int)FU_SMEM);

    detect_kernel<<<1, 32>>>((const unsigned int*)eidx);
    zero_kernel<<<(N_NODES * AD / 4 + 255) / 256, 256>>>();
    hist_kernel<<<(N_EDGES + 255) / 256, 256>>>(eidx);
    scan1_kernel<<<NBLK, SCAN_B>>>();
    scan2_kernel<<<1, 128>>>();
    scan3_kernel<<<NBLK, SCAN_B>>>();
    fill_kernel<<<(N_EDGES + 255) / 256, 256>>>(eidx);
    edge_kernel<<<N_EDGES / 32 / EW, 256>>>(eattr, W_time, b_time);
    down_kernel<<<148, 512, DN_SMEM>>>(x, W_down, b_down);
    fuseup_kernel<<<148, 512, FU_SMEM>>>(x, W_fusion, b_fusion, W_up, b_up, out);
}